// round 3
// baseline (speedup 1.0000x reference)
#include <cuda_runtime.h>
#include <math.h>

// ---------------------------------------------------------------------------
// Constants fixed by setup_inputs
// ---------------------------------------------------------------------------
#define NF      32
#define XS      576        // 2*9*32 floats per node
#define NNODE   1024
#define NMOL    32
#define NATOM   32
#define EPM     992
#define NEDGE   31744

// ---------------------------------------------------------------------------
// Device scratch (static, no allocation)
// ---------------------------------------------------------------------------
__device__ float g_cg_dense[729];
__device__ float g_cg_val[768];
__device__ int   g_cg_idx[768];
__device__ int   g_cg_cstart[10];

__device__ float g_r[NEDGE];
__device__ float g_sh[NEDGE * 9];
__device__ float g_rad[NEDGE * 8];

__device__ float g_x[NNODE * XS];
__device__ float g_xEF[NNODE * XS];
__device__ float g_msg[NNODE * XS];
__device__ float g_q[NNODE];
__device__ float g_aE[NNODE];
__device__ float g_dip[NNODE * 3];

__host__ __device__ __forceinline__ int dm_of(int i) { return (i == 0) ? 0 : ((i < 4) ? 1 : 2); }

__device__ __forceinline__ float warp_sum(float v) {
#pragma unroll
    for (int o = 16; o; o >>= 1) v += __shfl_xor_sync(0xffffffffu, v, o);
    return v;
}
__device__ __forceinline__ float sigm(float x) { return 1.0f / (1.0f + expf(-x)); }

// ---------------------------------------------------------------------------
// Clebsch-Gordan construction (replicates reference _build_cg in float64)
// ---------------------------------------------------------------------------
struct Cx { double re, im; };
__device__ __forceinline__ Cx cmul(Cx a, Cx b) {
    Cx r; r.re = a.re * b.re - a.im * b.im; r.im = a.re * b.im + a.im * b.re; return r;
}
__device__ double dfact(int n) { double r = 1.0; for (int i = 2; i <= n; i++) r *= (double)i; return r; }

__device__ double dcgc(int j1, int m1, int j2, int m2, int J, int M) {
    if (m1 + m2 != M) return 0.0;
    int adiff = j1 - j2; if (adiff < 0) adiff = -adiff;
    if (J < adiff || J > j1 + j2) return 0.0;
    double pref = (2.0 * J + 1.0) * dfact(J + j1 - j2) * dfact(J - j1 + j2) * dfact(j1 + j2 - J)
                  / dfact(j1 + j2 + J + 1);
    pref *= dfact(J + M) * dfact(J - M) * dfact(j1 - m1) * dfact(j1 + m1) * dfact(j2 - m2) * dfact(j2 + m2);
    double s = 0.0;
    for (int k = 0; k <= j1 + j2; k++) {
        int d0 = j1 + j2 - J - k, d1 = j1 - m1 - k, d2 = j2 + m2 - k;
        int d3 = J - j2 + m1 + k, d4 = J - j1 - m2 + k;
        if (d0 < 0 || d1 < 0 || d2 < 0 || d3 < 0 || d4 < 0) continue;
        double t = 1.0 / (dfact(k) * dfact(d0) * dfact(d1) * dfact(d2) * dfact(d3) * dfact(d4));
        s += (k & 1) ? -t : t;
    }
    return sqrt(pref) * s;
}

// row rr of U(l): up to 2 complex entries. col index in [0, 2l].
__device__ int u_row(int l, int rr, int* col, Cx* val) {
    const double R2 = 0.70710678118654752440;
    if (rr == l) { col[0] = l; val[0].re = 1.0; val[0].im = 0.0; return 1; }
    if (rr > l) {
        int m = rr - l; double sg = (m & 1) ? -1.0 : 1.0;
        col[0] = l + m; val[0].re = sg * R2; val[0].im = 0.0;
        col[1] = l - m; val[1].re = R2;      val[1].im = 0.0;
        return 2;
    }
    int m = l - rr; double sg = (m & 1) ? -1.0 : 1.0;
    col[0] = l - m; val[0].re = 0.0; val[0].im = R2;
    col[1] = l + m; val[1].re = 0.0; val[1].im = -sg * R2;
    return 2;
}

// 729 threads over 3 blocks of 243 — avoids the per-block register ceiling
// that the previous single-block 736-thread launch hit.
__global__ void cg_compute_kernel() {
    int tid = blockIdx.x * blockDim.x + threadIdx.x;
    if (tid >= 729) return;
    int A = tid / 81, Bc = (tid / 9) % 9, C = tid % 9;
    int l1 = dm_of(A), l2 = dm_of(Bc), l3 = dm_of(C);
    int a = A - l1 * l1, b = Bc - l2 * l2, c = C - l3 * l3;
    double gre = 0.0, gim = 0.0;
    int ad = l1 - l2; if (ad < 0) ad = -ad;
    if (l3 >= ad && l3 <= l1 + l2) {
        int c1[2], c2[2], c3[2]; Cx v1[2], v2[2], v3[2];
        int n1 = u_row(l1, a, c1, v1);
        int n2 = u_row(l2, b, c2, v2);
        int n3 = u_row(l3, c, c3, v3);
        for (int i = 0; i < n1; i++)
            for (int j = 0; j < n2; j++)
                for (int k = 0; k < n3; k++) {
                    double cv = dcgc(l1, c1[i] - l1, l2, c2[j] - l2, l3, c3[k] - l3);
                    if (cv == 0.0) continue;
                    Cx p = cmul(v1[i], v2[j]);
                    Cx v3c; v3c.re = v3[k].re; v3c.im = -v3[k].im;
                    p = cmul(p, v3c);
                    gre += p.re * cv; gim += p.im * cv;
                }
    }
    double R = (fabs(gim) > fabs(gre)) ? gim : gre;
    g_cg_dense[tid] = (float)R;
}

__global__ void cg_compact_kernel() {
    int cnt = 0;
    for (int c = 0; c < 9; c++) {
        g_cg_cstart[c] = cnt;
        for (int a = 0; a < 9; a++)
            for (int b = 0; b < 9; b++) {
                float v = g_cg_dense[(a * 9 + b) * 9 + c];
                if (fabsf(v) > 1e-7f) {
                    int lidx = dm_of(a) * 9 + dm_of(b) * 3 + dm_of(c);
                    int bodd = (b >= 1 && b <= 3) ? 1 : 0;
                    g_cg_idx[cnt] = a | (b << 4) | (lidx << 8) | (bodd << 13);
                    g_cg_val[cnt] = v;
                    cnt++;
                }
            }
    }
    g_cg_cstart[9] = cnt;
}

// ---------------------------------------------------------------------------
// Edge precompute: r, spherical harmonics, radial basis
// ---------------------------------------------------------------------------
__global__ void edge_kernel(const float* __restrict__ pos,
                            const int* __restrict__ dst_idx,
                            const int* __restrict__ src_idx) {
    int e = blockIdx.x * blockDim.x + threadIdx.x;
    if (e >= NEDGE) return;
    int mol = e / EPM, k = e % EPM;
    int d = dst_idx[k] + mol * NATOM;
    int s = src_idx[k] + mol * NATOM;
    float dx = pos[s * 3 + 0] - pos[d * 3 + 0];
    float dy = pos[s * 3 + 1] - pos[d * 3 + 1];
    float dz = pos[s * 3 + 2] - pos[d * 3 + 2];
    float r = sqrtf(dx * dx + dy * dy + dz * dz);
    g_r[e] = r;
    float inv = 1.0f / (r + 1e-10f);
    float x = dx * inv, y = dy * inv, z = dz * inv;
    const float s3 = 1.7320508075688772f;
    g_sh[e * 9 + 0] = 1.0f;
    g_sh[e * 9 + 1] = y;
    g_sh[e * 9 + 2] = z;
    g_sh[e * 9 + 3] = x;
    g_sh[e * 9 + 4] = s3 * x * y;
    g_sh[e * 9 + 5] = s3 * y * z;
    g_sh[e * 9 + 6] = 0.5f * (3.0f * z * z - 1.0f);
    g_sh[e * 9 + 7] = s3 * x * z;
    g_sh[e * 9 + 8] = 0.5f * s3 * (x * x - y * y);

    float fb = 1.0f / (1.0f + r);
    float omf = 1.0f - fb;
    float u2 = (r * 0.2f) * (r * 0.2f);
    float inner = fmaxf(1.0f - u2, 1e-6f);
    float cut = (r < 5.0f) ? expf(1.0f - 1.0f / inner) : 0.0f;
    const float binom[8] = {1.f, 7.f, 21.f, 35.f, 35.f, 21.f, 7.f, 1.f};
    float fp[8], op[8];
    fp[0] = 1.0f; op[0] = 1.0f;
#pragma unroll
    for (int i = 1; i < 8; i++) { fp[i] = fp[i - 1] * fb; op[i] = op[i - 1] * omf; }
#pragma unroll
    for (int i = 0; i < 8; i++)
        g_rad[e * 8 + i] = binom[i] * fp[i] * op[7 - i] * cut;
}

// ---------------------------------------------------------------------------
// State init
// ---------------------------------------------------------------------------
__global__ void init_kernel(const int* __restrict__ Zarr,
                            const float* __restrict__ embed,
                            const float* __restrict__ Ef) {
    int node = blockIdx.x;
    int lane = threadIdx.x;
    int mol = node >> 5;
    int Z = Zarr[node];
    float* x = g_x + node * XS;
    float* xe = g_xEF + node * XS;
#pragma unroll
    for (int p = 0; p < 2; p++)
#pragma unroll
        for (int m = 0; m < 9; m++) {
            float xv = (p == 0 && m == 0) ? embed[Z * NF + lane] : 0.0f;
            float ev = (m >= 1 && m <= 3) ? Ef[mol * 3 + (m - 1)] : 0.0f;
            x[(p * 9 + m) * NF + lane] = xv;
            xe[(p * 9 + m) * NF + lane] = ev;
        }
}

// ---------------------------------------------------------------------------
// Message pass: one block per destination node, 2 warps (one per parity)
// ---------------------------------------------------------------------------
__global__ void __launch_bounds__(64) msg_kernel(const float* __restrict__ Wmp, int iter, int md) {
    int node = blockIdx.x;
    int w = threadIdx.x >> 5;        // parity this warp accumulates
    int f = threadIdx.x & 31;
    int mol = node >> 5, datom = node & 31;
    __shared__ float sA[2 * 81 * 32];

    float wmp[3][8];
#pragma unroll
    for (int l = 0; l < 3; l++)
#pragma unroll
        for (int nb = 0; nb < 8; nb++)
            wmp[l][nb] = Wmp[((iter * 3 + l) * 8 + nb) * NF + f];

    float A[81];
#pragma unroll
    for (int i = 0; i < 81; i++) A[i] = 0.0f;

    int ebase = mol * EPM + datom * 31;
    for (int t = 0; t < 31; t++) {
        int e = ebase + t;
        int satom = t + (t >= datom ? 1 : 0);
        const float* xs = g_x + (mol * NATOM + satom) * XS + w * 288;
        float rad[8], sh9[9];
#pragma unroll
        for (int i = 0; i < 8; i++) rad[i] = g_rad[e * 8 + i];
#pragma unroll
        for (int i = 0; i < 9; i++) sh9[i] = g_sh[e * 9 + i];
        float R0 = 0.f, R1 = 0.f, R2v = 0.f;
#pragma unroll
        for (int nb = 0; nb < 8; nb++) {
            R0 += rad[nb] * wmp[0][nb];
            R1 += rad[nb] * wmp[1][nb];
            R2v += rad[nb] * wmp[2][nb];
        }
        float g[9];
        g[0] = sh9[0] * R0;
        g[1] = sh9[1] * R1; g[2] = sh9[2] * R1; g[3] = sh9[3] * R1;
        g[4] = sh9[4] * R2v; g[5] = sh9[5] * R2v; g[6] = sh9[6] * R2v;
        g[7] = sh9[7] * R2v; g[8] = sh9[8] * R2v;
        float xv[9];
#pragma unroll
        for (int a = 0; a < 9; a++) xv[a] = xs[a * NF + f];
#pragma unroll
        for (int a = 0; a < 9; a++)
#pragma unroll
            for (int b = 0; b < 9; b++)
                A[a * 9 + b] += xv[a] * g[b];
    }
#pragma unroll
    for (int i = 0; i < 81; i++) sA[(w * 81 + i) * NF + f] = A[i];
    __syncthreads();

    int cs[10];
#pragma unroll
    for (int i = 0; i < 10; i++) cs[i] = g_cg_cstart[i];

    float* ymsg = g_msg + node * XS + w * 288;
#pragma unroll
    for (int c = 0; c < 9; c++) {
        float acc = 0.0f;
        if (md != 0 || c == 0) {
            for (int j = cs[c]; j < cs[c + 1]; j++) {
                int pk = g_cg_idx[j];
                float v = g_cg_val[j];
                int a = pk & 15, b = (pk >> 4) & 15, bodd = (pk >> 13) & 1;
                int p = bodd ^ w;
                acc += v * sA[(p * 81 + a * 9 + b) * NF + f];
            }
        }
        ymsg[c * NF + f] = acc;
    }
}

// ---------------------------------------------------------------------------
// Dense (per-row F x F matmul) via shuffle broadcast; in-place on 2x9 rows
// ---------------------------------------------------------------------------
__device__ __forceinline__ void dense18(float X[2][9], const float* __restrict__ W, int lane) {
    float wc[32];
#pragma unroll
    for (int k = 0; k < 32; k++) wc[k] = W[k * NF + lane];
#pragma unroll
    for (int p = 0; p < 2; p++)
#pragma unroll
        for (int m = 0; m < 9; m++) {
            float v = X[p][m];
            float acc = 0.0f;
#pragma unroll
            for (int k = 0; k < 32; k++)
                acc += __shfl_sync(0xffffffffu, v, k) * wc[k];
            X[p][m] = acc;
        }
}

// Sparse CG couple with per-path weights Wp[27][F]; inputs staged per-lane
__device__ __forceinline__ void couple18(const float* sA, const float* sB,
                                         const float* __restrict__ Wp,
                                         const int* cs, int lane, float O[2][9]) {
#pragma unroll
    for (int c = 0; c < 9; c++) {
        float a0 = 0.0f, a1 = 0.0f;
        for (int j = cs[c]; j < cs[c + 1]; j++) {
            int pk = g_cg_idx[j];
            float v = g_cg_val[j];
            int a = pk & 15, b = (pk >> 4) & 15, lidx = (pk >> 8) & 31;
            float wv = v * Wp[lidx * NF + lane];
            float x10 = sA[a * NF + lane],        x11 = sA[(9 + a) * NF + lane];
            float x20 = sB[b * NF + lane],        x21 = sB[(9 + b) * NF + lane];
            a0 += wv * (x10 * x20 + x11 * x21);
            a1 += wv * (x10 * x21 + x11 * x20);
        }
        O[0][c] = a0; O[1][c] = a1;
    }
}

// ---------------------------------------------------------------------------
// Node update (one warp per node): residual, silu, dense, couple with xEF,
// tensor_dense, final residual
// ---------------------------------------------------------------------------
__global__ void __launch_bounds__(32) node_update_kernel(
    const float* __restrict__ Wd, const float* __restrict__ bd,
    const float* __restrict__ Wt,
    const float* __restrict__ Wtd1, const float* __restrict__ Wtd2,
    const float* __restrict__ Wtdp, int iter) {
    int node = blockIdx.x;
    int lane = threadIdx.x;
    __shared__ float sA[2 * 9 * 32];
    __shared__ float sB[2 * 9 * 32];

    int cs[10];
#pragma unroll
    for (int i = 0; i < 10; i++) cs[i] = g_cg_cstart[i];

    float X[2][9], Y[2][9];
    const float* xg = g_x + node * XS;
    const float* yg = g_msg + node * XS;
#pragma unroll
    for (int p = 0; p < 2; p++)
#pragma unroll
        for (int m = 0; m < 9; m++) {
            X[p][m] = xg[(p * 9 + m) * NF + lane];
            Y[p][m] = yg[(p * 9 + m) * NF + lane];
            X[p][m] += Y[p][m];
        }

    // silu
    float gate = sigm(X[0][0]);
#pragma unroll
    for (int p = 0; p < 2; p++)
#pragma unroll
        for (int m = 0; m < 9; m++) X[p][m] *= gate;

    // dense Wd + bias, silu
    dense18(X, Wd + iter * NF * NF, lane);
    X[0][0] += bd[iter * NF + lane];
    gate = sigm(X[0][0]);
#pragma unroll
    for (int p = 0; p < 2; p++)
#pragma unroll
        for (int m = 0; m < 9; m++) X[p][m] *= gate;

    // couple(x, xEF, Wt, 2) -> new xEF
    float* xeg = g_xEF + node * XS;
#pragma unroll
    for (int p = 0; p < 2; p++)
#pragma unroll
        for (int m = 0; m < 9; m++) {
            sA[(p * 9 + m) * NF + lane] = X[p][m];
            sB[(p * 9 + m) * NF + lane] = xeg[(p * 9 + m) * NF + lane];
        }
    float O[2][9];
    couple18(sA, sB, Wt + iter * 27 * NF, cs, lane, O);
#pragma unroll
    for (int p = 0; p < 2; p++)
#pragma unroll
        for (int m = 0; m < 9; m++) {
            xeg[(p * 9 + m) * NF + lane] = O[p][m];
            X[p][m] += O[p][m];
        }

    // tensor_dense: u = X@Wtd1, v = X@Wtd2, couple(u, v, Wtdp, 2)
    float U[2][9], V[2][9];
#pragma unroll
    for (int p = 0; p < 2; p++)
#pragma unroll
        for (int m = 0; m < 9; m++) { U[p][m] = X[p][m]; V[p][m] = X[p][m]; }
    dense18(U, Wtd1 + iter * NF * NF, lane);
    dense18(V, Wtd2 + iter * NF * NF, lane);
#pragma unroll
    for (int p = 0; p < 2; p++)
#pragma unroll
        for (int m = 0; m < 9; m++) {
            sA[(p * 9 + m) * NF + lane] = U[p][m];
            sB[(p * 9 + m) * NF + lane] = V[p][m];
        }
    couple18(sA, sB, Wtdp + iter * 27 * NF, cs, lane, O);

    // x = couple_result + y; store
    float* xo = g_x + node * XS;
#pragma unroll
    for (int p = 0; p < 2; p++)
#pragma unroll
        for (int m = 0; m < 9; m++)
            xo[(p * 9 + m) * NF + lane] = O[p][m] + Y[p][m];
}

// ---------------------------------------------------------------------------
// Readout: 5 dense layers, charges, site energies, atomic dipoles
// ---------------------------------------------------------------------------
__global__ void __launch_bounds__(32) readout_kernel(
    const float* __restrict__ Wh, const float* __restrict__ bh,
    const float* __restrict__ Wq,
    const float* __restrict__ Wdip1, const float* __restrict__ Wdip2,
    const float* __restrict__ Wdipp, const float* __restrict__ wdip,
    const float* __restrict__ We, const float* __restrict__ be,
    const float* __restrict__ element_bias, const int* __restrict__ Zarr) {
    int node = blockIdx.x;
    int lane = threadIdx.x;
    __shared__ float sA[2 * 9 * 32];
    __shared__ float sB[2 * 9 * 32];

    int cs[10];
#pragma unroll
    for (int i = 0; i < 10; i++) cs[i] = g_cg_cstart[i];

    float X[2][9];
    const float* xg = g_x + node * XS;
#pragma unroll
    for (int p = 0; p < 2; p++)
#pragma unroll
        for (int m = 0; m < 9; m++) X[p][m] = xg[(p * 9 + m) * NF + lane];

#pragma unroll
    for (int i = 0; i < 4; i++) {
        dense18(X, Wh + i * NF * NF, lane);
        X[0][0] += bh[i * NF + lane];
        float gate = sigm(X[0][0]);
#pragma unroll
        for (int p = 0; p < 2; p++)
#pragma unroll
            for (int m = 0; m < 9; m++) X[p][m] *= gate;
    }
    dense18(X, Wh + 4 * NF * NF, lane);
    X[0][0] += bh[4 * NF + lane];

    float scal = X[0][0];
    float q = warp_sum(scal * Wq[lane]);
    float ae = warp_sum(scal * We[lane]);

    // xd: keep [0,0] and [1,1:4]; tensor_dense with Wdip1/2/Wdipp (maxdeg=1)
    float U[2][9], V[2][9];
#pragma unroll
    for (int p = 0; p < 2; p++)
#pragma unroll
        for (int m = 0; m < 9; m++) { U[p][m] = 0.0f; }
    U[0][0] = X[0][0];
    U[1][1] = X[1][1]; U[1][2] = X[1][2]; U[1][3] = X[1][3];
#pragma unroll
    for (int p = 0; p < 2; p++)
#pragma unroll
        for (int m = 0; m < 9; m++) V[p][m] = U[p][m];

    dense18(U, Wdip1, lane);
    dense18(V, Wdip2, lane);
#pragma unroll
    for (int p = 0; p < 2; p++)
#pragma unroll
        for (int m = 0; m < 9; m++) {
            sA[(p * 9 + m) * NF + lane] = U[p][m];
            sB[(p * 9 + m) * NF + lane] = V[p][m];
        }
    float O[2][9];
    couple18(sA, sB, Wdipp, cs, lane, O);

    float d0 = warp_sum(O[1][1] * wdip[lane]);
    float d1 = warp_sum(O[1][2] * wdip[lane]);
    float d2 = warp_sum(O[1][3] * wdip[lane]);

    if (lane == 0) {
        g_q[node] = q;
        g_aE[node] = ae + be[0] + element_bias[Zarr[node]];
        g_dip[node * 3 + 0] = d0;
        g_dip[node * 3 + 1] = d1;
        g_dip[node * 3 + 2] = d2;
    }
}

// ---------------------------------------------------------------------------
// Per-molecule reduction: energy (+Coulomb), dipole
// ---------------------------------------------------------------------------
__global__ void __launch_bounds__(32) reduce_kernel(
    const float* __restrict__ pos,
    const int* __restrict__ dst_idx, const int* __restrict__ src_idx,
    float* __restrict__ out) {
    int mol = blockIdx.x;
    int lane = threadIdx.x;
    int node = mol * NATOM + lane;

    float px = pos[node * 3 + 0], py = pos[node * 3 + 1], pz = pos[node * 3 + 2];
    float cx = warp_sum(px) * (1.0f / 32.0f);
    float cy = warp_sum(py) * (1.0f / 32.0f);
    float cz = warp_sum(pz) * (1.0f / 32.0f);

    float e = warp_sum(g_aE[node]);
    float q = g_q[node];
    float dx = warp_sum(q * (px - cx) + g_dip[node * 3 + 0]);
    float dy = warp_sum(q * (py - cy) + g_dip[node * 3 + 1]);
    float dz = warp_sum(q * (pz - cz) + g_dip[node * 3 + 2]);

    float cacc = 0.0f;
    for (int t = 0; t < 31; t++) {
        int k = t * 32 + lane;
        int e_idx = mol * EPM + k;
        int s = src_idx[k] + mol * NATOM;
        int d = dst_idx[k] + mol * NATOM;
        cacc += g_q[s] * g_q[d] / (g_r[e_idx] + 1e-10f);
    }
    float coul = warp_sum(cacc) * 0.5f;

    if (lane == 0) {
        out[mol] = e + coul * 14.399645f;
        out[NMOL + mol * 3 + 0] = dx;
        out[NMOL + mol * 3 + 1] = dy;
        out[NMOL + mol * 3 + 2] = dz;
    }
}

// ---------------------------------------------------------------------------
// Launch
// ---------------------------------------------------------------------------
extern "C" void kernel_launch(void* const* d_in, const int* in_sizes, int n_in,
                              void* d_out, int out_size) {
    // Detect whether batch_size (scalar int) is materialized at index 5.
    int sft = (n_in >= 24) ? 1 : 0;

    const int*   Zarr   = (const int*)  d_in[0];
    const float* pos    = (const float*)d_in[1];
    const float* Ef     = (const float*)d_in[2];
    const int*   dsti   = (const int*)  d_in[3];
    const int*   srci   = (const int*)  d_in[4];
    const float* embed  = (const float*)d_in[5 + sft];
    const float* Wmp    = (const float*)d_in[6 + sft];
    const float* Wd     = (const float*)d_in[7 + sft];
    const float* bd     = (const float*)d_in[8 + sft];
    const float* Wt     = (const float*)d_in[9 + sft];
    const float* Wtd1   = (const float*)d_in[10 + sft];
    const float* Wtd2   = (const float*)d_in[11 + sft];
    const float* Wtdp   = (const float*)d_in[12 + sft];
    const float* Wh     = (const float*)d_in[13 + sft];
    const float* bh     = (const float*)d_in[14 + sft];
    const float* Wq     = (const float*)d_in[15 + sft];
    const float* Wdip1  = (const float*)d_in[16 + sft];
    const float* Wdip2  = (const float*)d_in[17 + sft];
    const float* Wdipp  = (const float*)d_in[18 + sft];
    const float* wdip   = (const float*)d_in[19 + sft];
    const float* We     = (const float*)d_in[20 + sft];
    const float* be     = (const float*)d_in[21 + sft];
    const float* ebias  = (const float*)d_in[22 + sft];
    float* out = (float*)d_out;

    cg_compute_kernel<<<3, 243>>>();
    cg_compact_kernel<<<1, 1>>>();
    edge_kernel<<<(NEDGE + 255) / 256, 256>>>(pos, dsti, srci);
    init_kernel<<<NNODE, 32>>>(Zarr, embed, Ef);

    for (int it = 0; it < 3; it++) {
        int md = (it < 2) ? 2 : 0;
        msg_kernel<<<NNODE, 64>>>(Wmp, it, md);
        node_update_kernel<<<NNODE, 32>>>(Wd, bd, Wt, Wtd1, Wtd2, Wtdp, it);
    }
    readout_kernel<<<NNODE, 32>>>(Wh, bh, Wq, Wdip1, Wdip2, Wdipp, wdip, We, be, ebias, Zarr);
    reduce_kernel<<<NMOL, 32>>>(pos, dsti, srci, out);
    (void)in_sizes; (void)out_size;
}

// round 5
// speedup vs baseline: 3.0240x; 3.0240x over previous
#include <cuda_runtime.h>
#include <math.h>

// ---------------------------------------------------------------------------
// Constants fixed by setup_inputs
// ---------------------------------------------------------------------------
#define NF      32
#define XS      576        // 2*9*32 floats per node
#define NNODE   1024
#define NMOL    32
#define NATOM   32
#define EPM     992
#define NEDGE   31744

// ---------------------------------------------------------------------------
// Compile-time Clebsch-Gordan per-entry evaluation (replicates _build_cg).
// All functions are __host__ __device__ constexpr so device code can form
// constant expressions from them WITHOUT --expt-relaxed-constexpr.
// ---------------------------------------------------------------------------
namespace cg {

__host__ __device__ constexpr double fact(int n) {
    double r = 1.0; for (int i = 2; i <= n; i++) r *= (double)i; return r;
}

__host__ __device__ constexpr double csqrt(double x) {
    if (x <= 0.0) return 0.0;
    double g = (x > 1.0) ? x : 1.0;
    for (int i = 0; i < 100; i++) g = 0.5 * (g + x / g);
    return g;
}

__host__ __device__ constexpr double cgc(int j1, int m1, int j2, int m2, int J, int M) {
    if (m1 + m2 != M) return 0.0;
    int ad = j1 - j2; if (ad < 0) ad = -ad;
    if (J < ad || J > j1 + j2) return 0.0;
    double pref = (2.0 * J + 1.0) * fact(J + j1 - j2) * fact(J - j1 + j2) * fact(j1 + j2 - J)
                  / fact(j1 + j2 + J + 1);
    pref *= fact(J + M) * fact(J - M) * fact(j1 - m1) * fact(j1 + m1) * fact(j2 - m2) * fact(j2 + m2);
    double s = 0.0;
    for (int k = 0; k <= j1 + j2; k++) {
        int d0 = j1 + j2 - J - k, d1 = j1 - m1 - k, d2 = j2 + m2 - k;
        int d3 = J - j2 + m1 + k, d4 = J - j1 - m2 + k;
        if (d0 < 0 || d1 < 0 || d2 < 0 || d3 < 0 || d4 < 0) continue;
        double t = 1.0 / (fact(k) * fact(d0) * fact(d1) * fact(d2) * fact(d3) * fact(d4));
        s += (k & 1) ? -t : t;
    }
    return csqrt(pref) * s;
}

struct C2 { double re, im; };
struct URow { int n; int col[2]; C2 v[2]; };

__host__ __device__ constexpr URow urow(int l, int rr) {
    URow u{};
    const double R2 = 0.70710678118654752440;
    if (rr == l) { u.n = 1; u.col[0] = l; u.v[0].re = 1.0; u.v[0].im = 0.0; return u; }
    if (rr > l) {
        int m = rr - l; double sg = (m & 1) ? -1.0 : 1.0;
        u.n = 2;
        u.col[0] = l + m; u.v[0].re = sg * R2; u.v[0].im = 0.0;
        u.col[1] = l - m; u.v[1].re = R2;      u.v[1].im = 0.0;
        return u;
    }
    int m = l - rr; double sg = (m & 1) ? -1.0 : 1.0;
    u.n = 2;
    u.col[0] = l - m; u.v[0].re = 0.0; u.v[0].im = R2;
    u.col[1] = l + m; u.v[1].re = 0.0; u.v[1].im = -sg * R2;
    return u;
}

__host__ __device__ constexpr int dm(int i) { return (i == 0) ? 0 : ((i < 4) ? 1 : 2); }

// Single entry of the real-basis CG tensor CG[A, B, C] (A,B,C in 0..8).
__host__ __device__ constexpr float cg_entry(int A, int B, int C) {
    int l1 = dm(A), l2 = dm(B), l3 = dm(C);
    int a = A - l1 * l1, b = B - l2 * l2, c = C - l3 * l3;
    double gre = 0.0, gim = 0.0;
    int ad = l1 - l2; if (ad < 0) ad = -ad;
    if (l3 >= ad && l3 <= l1 + l2) {
        URow u1 = urow(l1, a), u2 = urow(l2, b), u3 = urow(l3, c);
        for (int i = 0; i < u1.n; i++)
            for (int j = 0; j < u2.n; j++)
                for (int k = 0; k < u3.n; k++) {
                    double cv = cgc(l1, u1.col[i] - l1, l2, u2.col[j] - l2,
                                    l3, u3.col[k] - l3);
                    if (cv == 0.0) continue;
                    double pre = u1.v[i].re * u2.v[j].re - u1.v[i].im * u2.v[j].im;
                    double pim = u1.v[i].re * u2.v[j].im + u1.v[i].im * u2.v[j].re;
                    double re = pre * u3.v[k].re + pim * u3.v[k].im;   // * conj(v3)
                    double im = pim * u3.v[k].re - pre * u3.v[k].im;
                    gre += re * cv; gim += im * cv;
                }
    }
    double agre = (gre < 0) ? -gre : gre;
    double agim = (gim < 0) ? -gim : gim;
    double R = (agim > agre) ? gim : gre;
    return (float)R;
}

} // namespace cg

// ---------------------------------------------------------------------------
// Device scratch (static, no allocation)
// ---------------------------------------------------------------------------
__device__ float g_r[NEDGE];
__device__ float g_sh[NEDGE * 9];
__device__ float g_rad[NEDGE * 8];

__device__ float g_x[NNODE * XS];
__device__ float g_xEF[NNODE * XS];
__device__ float g_msg[NNODE * XS];
__device__ float g_q[NNODE];
__device__ float g_aE[NNODE];
__device__ float g_dip[NNODE * 3];

__device__ __forceinline__ float warp_sum(float v) {
#pragma unroll
    for (int o = 16; o; o >>= 1) v += __shfl_xor_sync(0xffffffffu, v, o);
    return v;
}
__device__ __forceinline__ float sigm(float x) { return 1.0f / (1.0f + expf(-x)); }

// ---------------------------------------------------------------------------
// Compile-time CG contraction for message pass: y[c] += CG[a,b,c] * A[a*9+b]
// MD==2 -> all c; MD==0 -> only c==0.
// ---------------------------------------------------------------------------
template<int AB, int C, int MD>
__device__ __forceinline__ void cg_contract_c(const float (&A)[81], float (&y)[9]) {
    if constexpr (C < 9) {
        constexpr float v = cg::cg_entry(AB / 9, AB % 9, C);
        constexpr bool keep = (MD == 2) || (C == 0);
        if constexpr (v != 0.0f && keep) { y[C] += v * A[AB]; }
        cg_contract_c<AB, C + 1, MD>(A, y);
    }
}
template<int AB, int MD>
__device__ __forceinline__ void cg_contract_ab(const float (&A)[81], float (&y)[9]) {
    if constexpr (AB < 81) {
        cg_contract_c<AB, 0, MD>(A, y);
        cg_contract_ab<AB + 1, MD>(A, y);
    }
}

// ---------------------------------------------------------------------------
// Compile-time weighted couple: both parities, register-resident.
// O0[c] += CG*Wp*(U0[a]V0[b] + U1[a]V1[b]);  O1[c] += CG*Wp*(U0[a]V1[b]+U1[a]V0[b])
// MAXC=9 (maxdeg 2) or 4 (maxdeg 1).
// ---------------------------------------------------------------------------
template<int AB, int C, int MAXC>
__device__ __forceinline__ void couple_c(const float (&U0)[9], const float (&U1)[9],
                                         const float (&V0)[9], const float (&V1)[9],
                                         const float (&wt)[27],
                                         float (&O0)[9], float (&O1)[9]) {
    if constexpr (C < MAXC) {
        constexpr int a = AB / 9;
        constexpr int b = AB % 9;
        constexpr float v = cg::cg_entry(a, b, C);
        if constexpr (v != 0.0f) {
            constexpr int lidx = cg::dm(a) * 9 + cg::dm(b) * 3 + cg::dm(C);
            float wv = v * wt[lidx];
            O0[C] += wv * (U0[a] * V0[b] + U1[a] * V1[b]);
            O1[C] += wv * (U0[a] * V1[b] + U1[a] * V0[b]);
        }
        couple_c<AB, C + 1, MAXC>(U0, U1, V0, V1, wt, O0, O1);
    }
}
template<int AB, int MAXC>
__device__ __forceinline__ void couple_ab(const float (&U0)[9], const float (&U1)[9],
                                          const float (&V0)[9], const float (&V1)[9],
                                          const float (&wt)[27],
                                          float (&O0)[9], float (&O1)[9]) {
    if constexpr (AB < 81) {
        couple_c<AB, 0, MAXC>(U0, U1, V0, V1, wt, O0, O1);
        couple_ab<AB + 1, MAXC>(U0, U1, V0, V1, wt, O0, O1);
    }
}
template<int MAXC>
__device__ __forceinline__ void couple_reg(const float (&U0)[9], const float (&U1)[9],
                                           const float (&V0)[9], const float (&V1)[9],
                                           const float (&wt)[27],
                                           float (&O0)[9], float (&O1)[9]) {
#pragma unroll
    for (int c = 0; c < 9; c++) { O0[c] = 0.0f; O1[c] = 0.0f; }
    couple_ab<0, MAXC>(U0, U1, V0, V1, wt, O0, O1);
}

// ---------------------------------------------------------------------------
// Edge precompute: r, spherical harmonics, radial basis
// ---------------------------------------------------------------------------
__global__ void edge_kernel(const float* __restrict__ pos,
                            const int* __restrict__ dst_idx,
                            const int* __restrict__ src_idx) {
    int e = blockIdx.x * blockDim.x + threadIdx.x;
    if (e >= NEDGE) return;
    int mol = e / EPM, k = e % EPM;
    int d = dst_idx[k] + mol * NATOM;
    int s = src_idx[k] + mol * NATOM;
    float dx = pos[s * 3 + 0] - pos[d * 3 + 0];
    float dy = pos[s * 3 + 1] - pos[d * 3 + 1];
    float dz = pos[s * 3 + 2] - pos[d * 3 + 2];
    float r = sqrtf(dx * dx + dy * dy + dz * dz);
    g_r[e] = r;
    float inv = 1.0f / (r + 1e-10f);
    float x = dx * inv, y = dy * inv, z = dz * inv;
    const float s3 = 1.7320508075688772f;
    g_sh[e * 9 + 0] = 1.0f;
    g_sh[e * 9 + 1] = y;
    g_sh[e * 9 + 2] = z;
    g_sh[e * 9 + 3] = x;
    g_sh[e * 9 + 4] = s3 * x * y;
    g_sh[e * 9 + 5] = s3 * y * z;
    g_sh[e * 9 + 6] = 0.5f * (3.0f * z * z - 1.0f);
    g_sh[e * 9 + 7] = s3 * x * z;
    g_sh[e * 9 + 8] = 0.5f * s3 * (x * x - y * y);

    float fb = 1.0f / (1.0f + r);
    float omf = 1.0f - fb;
    float u2 = (r * 0.2f) * (r * 0.2f);
    float inner = fmaxf(1.0f - u2, 1e-6f);
    float cut = (r < 5.0f) ? expf(1.0f - 1.0f / inner) : 0.0f;
    const float binom[8] = {1.f, 7.f, 21.f, 35.f, 35.f, 21.f, 7.f, 1.f};
    float fp[8], op[8];
    fp[0] = 1.0f; op[0] = 1.0f;
#pragma unroll
    for (int i = 1; i < 8; i++) { fp[i] = fp[i - 1] * fb; op[i] = op[i - 1] * omf; }
#pragma unroll
    for (int i = 0; i < 8; i++)
        g_rad[e * 8 + i] = binom[i] * fp[i] * op[7 - i] * cut;
}

// ---------------------------------------------------------------------------
// State init (8 nodes per block)
// ---------------------------------------------------------------------------
__global__ void __launch_bounds__(256) init_kernel(const int* __restrict__ Zarr,
                                                   const float* __restrict__ embed,
                                                   const float* __restrict__ Ef) {
    int node = blockIdx.x * 8 + (threadIdx.x >> 5);
    int lane = threadIdx.x & 31;
    int mol = node >> 5;
    int Z = Zarr[node];
    float* x = g_x + node * XS;
    float* xe = g_xEF + node * XS;
    float e0 = Ef[mol * 3 + 0], e1 = Ef[mol * 3 + 1], e2 = Ef[mol * 3 + 2];
#pragma unroll
    for (int p = 0; p < 2; p++)
#pragma unroll
        for (int m = 0; m < 9; m++) {
            float xv = (p == 0 && m == 0) ? embed[Z * NF + lane] : 0.0f;
            float ev = (m == 1) ? e0 : ((m == 2) ? e1 : ((m == 3) ? e2 : 0.0f));
            x[(p * 9 + m) * NF + lane] = xv;
            xe[(p * 9 + m) * NF + lane] = ev;
        }
}

// ---------------------------------------------------------------------------
// Message pass: one block per destination node, 2 warps (one per out-parity)
// ---------------------------------------------------------------------------
template<int MD>
__global__ void __launch_bounds__(64) msg_kernel(const float* __restrict__ Wmp, int iter) {
    int node = blockIdx.x;
    int w = threadIdx.x >> 5;        // output parity this warp produces
    int f = threadIdx.x & 31;
    int mol = node >> 5, datom = node & 31;

    float wmp0[8], wmp1[8], wmp2[8];
#pragma unroll
    for (int nb = 0; nb < 8; nb++) {
        wmp0[nb] = Wmp[((iter * 3 + 0) * 8 + nb) * NF + f];
        wmp1[nb] = Wmp[((iter * 3 + 1) * 8 + nb) * NF + f];
        wmp2[nb] = Wmp[((iter * 3 + 2) * 8 + nb) * NF + f];
    }

    float A[81];
#pragma unroll
    for (int i = 0; i < 81; i++) A[i] = 0.0f;

    int ebase = mol * EPM + datom * 31;
    int sameoff = w * 288;           // x parity == output parity (even-b terms)
    int flipoff = 288 - sameoff;     // opposite parity (odd-b terms)
    const float* xmol = g_x + mol * NATOM * XS;

    for (int t = 0; t < 31; t++) {
        int e = ebase + t;
        int satom = t + (t >= datom ? 1 : 0);
        const float* xs = xmol + satom * XS;

        float R0 = 0.f, R1 = 0.f, R2v = 0.f;
#pragma unroll
        for (int nb = 0; nb < 8; nb++) {
            float rv = g_rad[e * 8 + nb];
            R0 += rv * wmp0[nb];
            R1 += rv * wmp1[nb];
            R2v += rv * wmp2[nb];
        }
        float g[9];
#pragma unroll
        for (int b = 0; b < 9; b++) {
            float Rl = (b == 0) ? R0 : ((b < 4) ? R1 : R2v);
            g[b] = g_sh[e * 9 + b] * Rl;
        }
        float xsame[9], xflip[9];
#pragma unroll
        for (int a = 0; a < 9; a++) {
            xsame[a] = xs[sameoff + a * NF + f];
            xflip[a] = xs[flipoff + a * NF + f];
        }
#pragma unroll
        for (int a = 0; a < 9; a++)
#pragma unroll
            for (int b = 0; b < 9; b++) {
                float xa = (b >= 1 && b <= 3) ? xflip[a] : xsame[a];
                A[a * 9 + b] += xa * g[b];
            }
    }

    float y[9];
#pragma unroll
    for (int c = 0; c < 9; c++) y[c] = 0.0f;
    cg_contract_ab<0, MD>(A, y);

    float* ymsg = g_msg + node * XS + w * 288;
#pragma unroll
    for (int c = 0; c < 9; c++) ymsg[c * NF + f] = y[c];
}

// ---------------------------------------------------------------------------
// Dense (per-row F x F matmul) via shuffle broadcast; both parities in regs
// ---------------------------------------------------------------------------
__device__ __forceinline__ void dense2(float (&X0)[9], float (&X1)[9],
                                       const float* __restrict__ W, int lane) {
    float wc[32];
#pragma unroll
    for (int k = 0; k < 32; k++) wc[k] = W[k * NF + lane];
#pragma unroll
    for (int m = 0; m < 9; m++) {
        float v0 = X0[m], v1 = X1[m];
        float a0 = 0.0f, a1 = 0.0f;
#pragma unroll
        for (int k = 0; k < 32; k++) {
            a0 += __shfl_sync(0xffffffffu, v0, k) * wc[k];
            a1 += __shfl_sync(0xffffffffu, v1, k) * wc[k];
        }
        X0[m] = a0; X1[m] = a1;
    }
}

// ---------------------------------------------------------------------------
// Node update (4 nodes per block, one warp per node; fully register-resident)
// ---------------------------------------------------------------------------
__global__ void __launch_bounds__(128) node_update_kernel(
    const float* __restrict__ Wd, const float* __restrict__ bd,
    const float* __restrict__ Wt,
    const float* __restrict__ Wtd1, const float* __restrict__ Wtd2,
    const float* __restrict__ Wtdp, int iter) {
    int node = blockIdx.x * 4 + (threadIdx.x >> 5);
    int lane = threadIdx.x & 31;

    float X0[9], X1[9], Y0[9], Y1[9];
    const float* xg = g_x + node * XS;
    const float* yg = g_msg + node * XS;
#pragma unroll
    for (int m = 0; m < 9; m++) {
        Y0[m] = yg[m * NF + lane];
        Y1[m] = yg[(9 + m) * NF + lane];
        X0[m] = xg[m * NF + lane] + Y0[m];
        X1[m] = xg[(9 + m) * NF + lane] + Y1[m];
    }

    float gate = sigm(X0[0]);
#pragma unroll
    for (int m = 0; m < 9; m++) { X0[m] *= gate; X1[m] *= gate; }

    dense2(X0, X1, Wd + iter * NF * NF, lane);
    X0[0] += bd[iter * NF + lane];
    gate = sigm(X0[0]);
#pragma unroll
    for (int m = 0; m < 9; m++) { X0[m] *= gate; X1[m] *= gate; }

    // couple(x, xEF, Wt, maxdeg=2) -> new xEF, then x += xEF
    float E0[9], E1[9];
    float* xeg = g_xEF + node * XS;
#pragma unroll
    for (int m = 0; m < 9; m++) {
        E0[m] = xeg[m * NF + lane];
        E1[m] = xeg[(9 + m) * NF + lane];
    }
    float wt[27];
#pragma unroll
    for (int j = 0; j < 27; j++) wt[j] = Wt[(iter * 27 + j) * NF + lane];

    float O0[9], O1[9];
    couple_reg<9>(X0, X1, E0, E1, wt, O0, O1);
#pragma unroll
    for (int m = 0; m < 9; m++) {
        xeg[m * NF + lane] = O0[m];
        xeg[(9 + m) * NF + lane] = O1[m];
        X0[m] += O0[m];
        X1[m] += O1[m];
    }

    // tensor_dense: u = X@Wtd1, v = X@Wtd2, couple(u, v, Wtdp, maxdeg=2)
    float U0[9], U1[9], V0[9], V1[9];
#pragma unroll
    for (int m = 0; m < 9; m++) { U0[m] = X0[m]; U1[m] = X1[m]; V0[m] = X0[m]; V1[m] = X1[m]; }
    dense2(U0, U1, Wtd1 + iter * NF * NF, lane);
    dense2(V0, V1, Wtd2 + iter * NF * NF, lane);
#pragma unroll
    for (int j = 0; j < 27; j++) wt[j] = Wtdp[(iter * 27 + j) * NF + lane];
    couple_reg<9>(U0, U1, V0, V1, wt, O0, O1);

    float* xo = g_x + node * XS;
#pragma unroll
    for (int m = 0; m < 9; m++) {
        xo[m * NF + lane] = O0[m] + Y0[m];
        xo[(9 + m) * NF + lane] = O1[m] + Y1[m];
    }
}

// ---------------------------------------------------------------------------
// Readout (4 nodes per block, one warp per node)
// ---------------------------------------------------------------------------
__global__ void __launch_bounds__(128) readout_kernel(
    const float* __restrict__ Wh, const float* __restrict__ bh,
    const float* __restrict__ Wq,
    const float* __restrict__ Wdip1, const float* __restrict__ Wdip2,
    const float* __restrict__ Wdipp, const float* __restrict__ wdip,
    const float* __restrict__ We, const float* __restrict__ be,
    const float* __restrict__ element_bias, const int* __restrict__ Zarr) {
    int node = blockIdx.x * 4 + (threadIdx.x >> 5);
    int lane = threadIdx.x & 31;

    float X0[9], X1[9];
    const float* xg = g_x + node * XS;
#pragma unroll
    for (int m = 0; m < 9; m++) {
        X0[m] = xg[m * NF + lane];
        X1[m] = xg[(9 + m) * NF + lane];
    }

#pragma unroll
    for (int i = 0; i < 4; i++) {
        dense2(X0, X1, Wh + i * NF * NF, lane);
        X0[0] += bh[i * NF + lane];
        float gate = sigm(X0[0]);
#pragma unroll
        for (int m = 0; m < 9; m++) { X0[m] *= gate; X1[m] *= gate; }
    }
    dense2(X0, X1, Wh + 4 * NF * NF, lane);
    X0[0] += bh[4 * NF + lane];

    float scal = X0[0];
    float q = warp_sum(scal * Wq[lane]);
    float ae = warp_sum(scal * We[lane]);

    // xd: keep [0,0] and [1,1:4]; tensor_dense (maxdeg=1)
    float U0[9], U1[9], V0[9], V1[9];
#pragma unroll
    for (int m = 0; m < 9; m++) { U0[m] = 0.0f; U1[m] = 0.0f; }
    U0[0] = X0[0];
    U1[1] = X1[1]; U1[2] = X1[2]; U1[3] = X1[3];
#pragma unroll
    for (int m = 0; m < 9; m++) { V0[m] = U0[m]; V1[m] = U1[m]; }

    dense2(U0, U1, Wdip1, lane);
    dense2(V0, V1, Wdip2, lane);

    float wt[27];
#pragma unroll
    for (int j = 0; j < 27; j++) wt[j] = Wdipp[j * NF + lane];
    float O0[9], O1[9];
    couple_reg<4>(U0, U1, V0, V1, wt, O0, O1);

    float wd = wdip[lane];
    float d0 = warp_sum(O1[1] * wd);
    float d1 = warp_sum(O1[2] * wd);
    float d2 = warp_sum(O1[3] * wd);

    if (lane == 0) {
        g_q[node] = q;
        g_aE[node] = ae + be[0] + element_bias[Zarr[node]];
        g_dip[node * 3 + 0] = d0;
        g_dip[node * 3 + 1] = d1;
        g_dip[node * 3 + 2] = d2;
    }
}

// ---------------------------------------------------------------------------
// Per-molecule reduction: energy (+Coulomb), dipole
// ---------------------------------------------------------------------------
__global__ void __launch_bounds__(32) reduce_kernel(
    const float* __restrict__ pos,
    const int* __restrict__ dst_idx, const int* __restrict__ src_idx,
    float* __restrict__ out) {
    int mol = blockIdx.x;
    int lane = threadIdx.x;
    int node = mol * NATOM + lane;

    float px = pos[node * 3 + 0], py = pos[node * 3 + 1], pz = pos[node * 3 + 2];
    float cx = warp_sum(px) * (1.0f / 32.0f);
    float cy = warp_sum(py) * (1.0f / 32.0f);
    float cz = warp_sum(pz) * (1.0f / 32.0f);

    float e = warp_sum(g_aE[node]);
    float q = g_q[node];
    float dx = warp_sum(q * (px - cx) + g_dip[node * 3 + 0]);
    float dy = warp_sum(q * (py - cy) + g_dip[node * 3 + 1]);
    float dz = warp_sum(q * (pz - cz) + g_dip[node * 3 + 2]);

    float cacc = 0.0f;
    for (int t = 0; t < 31; t++) {
        int k = t * 32 + lane;
        int e_idx = mol * EPM + k;
        int s = src_idx[k] + mol * NATOM;
        int d = dst_idx[k] + mol * NATOM;
        cacc += g_q[s] * g_q[d] / (g_r[e_idx] + 1e-10f);
    }
    float coul = warp_sum(cacc) * 0.5f;

    if (lane == 0) {
        out[mol] = e + coul * 14.399645f;
        out[NMOL + mol * 3 + 0] = dx;
        out[NMOL + mol * 3 + 1] = dy;
        out[NMOL + mol * 3 + 2] = dz;
    }
}

// ---------------------------------------------------------------------------
// Launch
// ---------------------------------------------------------------------------
extern "C" void kernel_launch(void* const* d_in, const int* in_sizes, int n_in,
                              void* d_out, int out_size) {
    int sft = (n_in >= 24) ? 1 : 0;

    const int*   Zarr   = (const int*)  d_in[0];
    const float* pos    = (const float*)d_in[1];
    const float* Ef     = (const float*)d_in[2];
    const int*   dsti   = (const int*)  d_in[3];
    const int*   srci   = (const int*)  d_in[4];
    const float* embed  = (const float*)d_in[5 + sft];
    const float* Wmp    = (const float*)d_in[6 + sft];
    const float* Wd     = (const float*)d_in[7 + sft];
    const float* bd     = (const float*)d_in[8 + sft];
    const float* Wt     = (const float*)d_in[9 + sft];
    const float* Wtd1   = (const float*)d_in[10 + sft];
    const float* Wtd2   = (const float*)d_in[11 + sft];
    const float* Wtdp   = (const float*)d_in[12 + sft];
    const float* Wh     = (const float*)d_in[13 + sft];
    const float* bh     = (const float*)d_in[14 + sft];
    const float* Wq     = (const float*)d_in[15 + sft];
    const float* Wdip1  = (const float*)d_in[16 + sft];
    const float* Wdip2  = (const float*)d_in[17 + sft];
    const float* Wdipp  = (const float*)d_in[18 + sft];
    const float* wdip   = (const float*)d_in[19 + sft];
    const float* We     = (const float*)d_in[20 + sft];
    const float* be     = (const float*)d_in[21 + sft];
    const float* ebias  = (const float*)d_in[22 + sft];
    float* out = (float*)d_out;

    edge_kernel<<<(NEDGE + 255) / 256, 256>>>(pos, dsti, srci);
    init_kernel<<<NNODE / 8, 256>>>(Zarr, embed, Ef);

    msg_kernel<2><<<NNODE, 64>>>(Wmp, 0);
    node_update_kernel<<<NNODE / 4, 128>>>(Wd, bd, Wt, Wtd1, Wtd2, Wtdp, 0);
    msg_kernel<2><<<NNODE, 64>>>(Wmp, 1);
    node_update_kernel<<<NNODE / 4, 128>>>(Wd, bd, Wt, Wtd1, Wtd2, Wtdp, 1);
    msg_kernel<0><<<NNODE, 64>>>(Wmp, 2);
    node_update_kernel<<<NNODE / 4, 128>>>(Wd, bd, Wt, Wtd1, Wtd2, Wtdp, 2);

    readout_kernel<<<NNODE / 4, 128>>>(Wh, bh, Wq, Wdip1, Wdip2, Wdipp, wdip, We, be, ebias, Zarr);
    reduce_kernel<<<NMOL, 32>>>(pos, dsti, srci, out);
    (void)in_sizes; (void)out_size;
}